// round 8
// baseline (speedup 1.0000x reference)
#include <cuda_runtime.h>
#include <stdint.h>
#include <math.h>

#define NB 8192
#define ND 128
#define NS 16          // number of subjects
#define NBLK 32        // count/order blocks (NB/256)
#define TM 128
#define TN 128
#define TK 16
#define MARGIN 0.8f
#define EPSF 1e-6f
#define MAXP (NB + NS*128)   // padded slot capacity (each bucket 128-aligned)
#define MAXT 4096
#define PAIR_GRID 296

// ---------------- device scratch (no allocations allowed) ----------------
__device__ float               g_sq  [NB];                 // per-row squared norms (original order)
__device__ int                 g_order[MAXP];              // bucket slot -> original row (pads = 0)
__device__ float               g_sqp [MAXP];               // bucketized sq-norms
__device__ int                 g_labp[MAXP];               // bucketized labels
__device__ int                 g_perm[MAXP];               // bucketized original index
__device__ int                 g_bh  [NBLK * NS];          // per-block subject histograms
__device__ int                 g_bbase[NBLK * NS];         // per-block per-subject slot bases
__device__ int                 g_cnt_s[NS];
__device__ int                 g_poff [NS];
__device__ int                 g_tiles[MAXT];              // packed (s | ti<<8 | tj<<16)
__device__ int                 g_ntiles;
__device__ unsigned long long  g_pos[NB];   // packed (ordered_d2 << 32) | (~j) ; argmax
__device__ unsigned long long  g_neg[NB];   // packed (ordered_d2 << 32) | ( j) ; argmin
__device__ float               g_sum;
__device__ int                 g_cnt;

// monotone float -> uint32 map (total order preserved)
__device__ __forceinline__ unsigned int ordf(float f) {
    unsigned int u = __float_as_uint(f);
    return (u & 0x80000000u) ? ~u : (u | 0x80000000u);
}

// ---------------- k1: per-block histogram + row norms + sentinel init ----------------
__global__ __launch_bounds__(256) void count_kernel(const float* __restrict__ emb,
                                                    const int*   __restrict__ sbj) {
    __shared__ int h[NS];
    const int t = threadIdx.x;
    const int b = blockIdx.x;
    if (t < NS) h[t] = 0;
    __syncthreads();

    const int i = b * 256 + t;
    atomicAdd(&h[sbj[i]], 1);
    g_pos[i] = 0ull;
    g_neg[i] = ~0ull;

    // squared norm of row i (32 float4 loads, high MLP)
    const float4* row = reinterpret_cast<const float4*>(emb + (size_t)i * ND);
    float s = 0.f;
#pragma unroll
    for (int q = 0; q < ND / 4; q++) {
        float4 v = row[q];
        s += v.x * v.x + v.y * v.y + v.z * v.z + v.w * v.w;
    }
    g_sq[i] = s;

    // init pad-safe order entries (order_kernel overwrites real slots)
    for (int p = b * 256 + t; p < MAXP; p += NBLK * 256) g_order[p] = 0;

    __syncthreads();
    if (t < NS) g_bh[b * NS + t] = h[t];
    if (b == 0 && t == 0) { g_sum = 0.f; g_cnt = 0; }
}

// ---------------- k2: totals, offsets, per-block bases, tile worklist ----------------
__global__ void plan_kernel() {
    __shared__ int toff[NS], cshr[NS];
    int t = threadIdx.x;
    if (t < NS) {
        int c = 0;
        for (int b = 0; b < NBLK; b++) c += g_bh[b * NS + t];
        g_cnt_s[t] = c;
        cshr[t] = c;
    }
    __syncthreads();
    if (t == 0) {
        int acc = 0, tacc = 0;
        for (int s = 0; s < NS; s++) {
            int m = (cshr[s] + 127) >> 7;
            g_poff[s] = acc;  acc  += m << 7;
            toff[s]   = tacc; tacc += m * m;
        }
        g_ntiles = tacc;
    }
    __syncthreads();
    if (t < NS) {
        // per-block exclusive scan (slot bases include subject offset)
        int acc = g_poff[t];
        for (int b = 0; b < NBLK; b++) {
            g_bbase[b * NS + t] = acc;
            acc += g_bh[b * NS + t];
        }
        // tile list
        int m = (cshr[t] + 127) >> 7;
        int base = toff[t];
        for (int ti = 0; ti < m; ti++)
            for (int tj = 0; tj < m; tj++)
                g_tiles[base++] = t | (ti << 8) | (tj << 16);
    }
}

// ---------------- k3: slot assignment + bucketized metadata (no data copy) ----------------
__global__ __launch_bounds__(256) void order_kernel(const int* __restrict__ labels,
                                                    const int* __restrict__ sbj) {
    __shared__ int h[NS];
    const int t = threadIdx.x;
    const int b = blockIdx.x;
    if (t < NS) h[t] = 0;
    __syncthreads();

    const int i = b * 256 + t;
    const int s = sbj[i];
    const int r = atomicAdd(&h[s], 1);
    const int slot = g_bbase[b * NS + s] + r;
    g_order[slot] = i;
    g_labp [slot] = labels[i];
    g_perm [slot] = i;
    g_sqp  [slot] = g_sq[i];
}

// ---------------- k4: persistent fused Gram (f32x2) + masked argmax/argmin ----------------
__global__ __launch_bounds__(256) void pair_kernel(const float* __restrict__ emb) {
    __shared__ __align__(16) float As[TK][TM + 4];
    __shared__ __align__(16) float Bs[TK][TN + 4];
    __shared__ int   srcA[TM], srcB[TN];
    __shared__ int   rlab[TM], rperm[TM];
    __shared__ float rsq[TM];
    __shared__ int   clab[TN], cperm[TN];
    __shared__ float csq[TN];

    const int tid = threadIdx.x;
    const int tx  = tid & 15;   // column micro-block (lane bits 0..3)
    const int ty  = tid >> 4;   // row micro-block
    const int ntiles = g_ntiles;

    for (int t = blockIdx.x; t < ntiles; t += gridDim.x) {
        const int desc = g_tiles[t];
        const int s  = desc & 255;
        const int ti = (desc >> 8) & 255;
        const int tj = (desc >> 16) & 255;
        const int n    = g_cnt_s[s];
        const int base = g_poff[s];
        const int rbase = base + ti * TM;
        const int cbase = base + tj * TN;

        __syncthreads();   // previous tile's epilogue done before smem overwrite
        if (tid < TM) {
            srcA[tid]  = g_order[rbase + tid];
            srcB[tid]  = g_order[cbase + tid];
            rlab[tid]  = g_labp[rbase + tid];
            rsq[tid]   = g_sqp [rbase + tid];
            rperm[tid] = g_perm[rbase + tid];
            clab[tid]  = g_labp[cbase + tid];
            csq[tid]   = g_sqp [cbase + tid];
            cperm[tid] = g_perm[cbase + tid];
        }

        unsigned long long c2[8][4];
#pragma unroll
        for (int a = 0; a < 8; a++)
#pragma unroll
            for (int b = 0; b < 4; b++) c2[a][b] = 0ull;

        for (int kk = 0; kk < ND; kk += TK) {
            __syncthreads();
#pragma unroll
            for (int r = 0; r < 2; r++) {
                int l = tid + r * 256;          // 0..511
                int m = l >> 2;                 // 0..127
                int q = l & 3;                  // float4 index within TK chunk
                float4 v = *reinterpret_cast<const float4*>(emb + (size_t)srcA[m] * ND + kk + q * 4);
                As[q * 4 + 0][m] = v.x; As[q * 4 + 1][m] = v.y;
                As[q * 4 + 2][m] = v.z; As[q * 4 + 3][m] = v.w;
                float4 w = *reinterpret_cast<const float4*>(emb + (size_t)srcB[m] * ND + kk + q * 4);
                Bs[q * 4 + 0][m] = w.x; Bs[q * 4 + 1][m] = w.y;
                Bs[q * 4 + 2][m] = w.z; Bs[q * 4 + 3][m] = w.w;
            }
            __syncthreads();
#pragma unroll
            for (int k = 0; k < TK; k++) {
                unsigned long long rb2[4];
                const unsigned long long* bp =
                    reinterpret_cast<const unsigned long long*>(&Bs[k][tx * 8]);
#pragma unroll
                for (int b = 0; b < 4; b++) rb2[b] = bp[b];
                unsigned long long ra2[8];
#pragma unroll
                for (int a = 0; a < 8; a++) {
                    unsigned int rr = __float_as_uint(As[k][ty * 8 + a]);
                    asm("mov.b64 %0, {%1, %1};" : "=l"(ra2[a]) : "r"(rr));
                }
#pragma unroll
                for (int a = 0; a < 8; a++)
#pragma unroll
                    for (int b = 0; b < 4; b++)
                        asm("fma.rn.f32x2 %0, %1, %2, %0;"
                            : "+l"(c2[a][b]) : "l"(ra2[a]), "l"(rb2[b]));
            }
        }

        // epilogue: per-thread masked best keys, shuffle-reduce across tx, 1 atomic/row
#pragma unroll
        for (int a = 0; a < 8; a++) {
            const int  il     = ti * TM + ty * 8 + a;
            const bool rvalid = (il < n);
            const int   ll = rlab[ty * 8 + a];
            const float si = rsq [ty * 8 + a];
            const int   io = rperm[ty * 8 + a];
            unsigned long long kp = 0ull, kn = ~0ull;
#pragma unroll
            for (int b2 = 0; b2 < 4; b2++) {
                union { unsigned long long u; float2 f; } cv;
                cv.u = c2[a][b2];
#pragma unroll
                for (int hh = 0; hh < 2; hh++) {
                    const int bcol = tx * 8 + 2 * b2 + hh;
                    const int jl   = tj * TN + bcol;
                    if (rvalid && jl < n) {
                        const float d2v = si + csq[bcol] - 2.f * (hh ? cv.f.y : cv.f.x);
                        const int   jo  = cperm[bcol];
                        if (clab[bcol] == ll) {
                            if (jo != io) {
                                unsigned long long key =
                                    ((unsigned long long)ordf(d2v) << 32) |
                                    (unsigned long long)(0xFFFFFFFFu - (unsigned)jo);
                                if (key > kp) kp = key;   // ties -> smaller original j
                            }
                        } else {
                            unsigned long long key =
                                ((unsigned long long)ordf(d2v) << 32) |
                                (unsigned long long)(unsigned)jo;
                            if (key < kn) kn = key;       // ties -> smaller original j
                        }
                    }
                }
            }
            // reduce across the 16 tx lanes (lane bits 0..3); all lanes participate
#pragma unroll
            for (int o = 1; o < 16; o <<= 1) {
                unsigned long long op = __shfl_xor_sync(0xFFFFFFFFu, kp, o);
                unsigned long long on = __shfl_xor_sync(0xFFFFFFFFu, kn, o);
                if (op > kp) kp = op;
                if (on < kn) kn = on;
            }
            if (tx == 0 && rvalid) {
                if (kp != 0ull)  atomicMax(&g_pos[io], kp);
                if (kn != ~0ull) atomicMin(&g_neg[io], kn);
            }
        }
    }
}

// ---------------- k5: triplet distances + loss accumulation ----------------
__global__ void triplet_kernel(const float* __restrict__ emb) {
    const int gw   = (blockIdx.x * blockDim.x + threadIdx.x) >> 5;  // one warp per row
    const int lane = threadIdx.x & 31;
    if (gw >= NB) return;

    const unsigned long long kp = g_pos[gw];
    const unsigned long long kn = g_neg[gw];
    if (kp == 0ull || kn == ~0ull) return;   // invalid row

    const int p = (int)(0xFFFFFFFFu - (unsigned)kp);
    const int n = (int)(unsigned)kn;

    const float4* ri = reinterpret_cast<const float4*>(emb + (size_t)gw * ND);
    const float4* rp = reinterpret_cast<const float4*>(emb + (size_t)p  * ND);
    const float4* rn = reinterpret_cast<const float4*>(emb + (size_t)n  * ND);

    const float4 a4 = ri[lane];
    const float4 p4 = rp[lane];
    const float4 n4 = rn[lane];

    float dx, s1, s2;
    dx = a4.x - p4.x + EPSF; s1  = dx * dx;   // torch pairwise_distance eps quirk
    dx = a4.y - p4.y + EPSF; s1 += dx * dx;
    dx = a4.z - p4.z + EPSF; s1 += dx * dx;
    dx = a4.w - p4.w + EPSF; s1 += dx * dx;
    dx = a4.x - n4.x + EPSF; s2  = dx * dx;
    dx = a4.y - n4.y + EPSF; s2 += dx * dx;
    dx = a4.z - n4.z + EPSF; s2 += dx * dx;
    dx = a4.w - n4.w + EPSF; s2 += dx * dx;

#pragma unroll
    for (int o = 16; o > 0; o >>= 1) {
        s1 += __shfl_down_sync(0xFFFFFFFFu, s1, o);
        s2 += __shfl_down_sync(0xFFFFFFFFu, s2, o);
    }
    if (lane == 0) {
        float per = fmaxf(sqrtf(s1) - sqrtf(s2) + MARGIN, 0.f);
        atomicAdd(&g_sum, per);
        atomicAdd(&g_cnt, 1);
    }
}

// ---------------- k6: finalize ----------------
__global__ void finalize_kernel(float* __restrict__ out) {
    int   c = g_cnt;
    float s = g_sum;
    out[0] = (c > 0) ? s / (float)c : 0.f;
}

// ---------------- launch ----------------
extern "C" void kernel_launch(void* const* d_in, const int* in_sizes, int n_in,
                              void* d_out, int out_size) {
    const float* emb    = (const float*)d_in[0];
    const int*   labels = (const int*)d_in[1];
    const int*   sbj    = (const int*)d_in[2];
    float*       out    = (float*)d_out;

    count_kernel  <<<NBLK, 256>>>(emb, sbj);
    plan_kernel   <<<1, 256>>>();
    order_kernel  <<<NBLK, 256>>>(labels, sbj);
    pair_kernel   <<<PAIR_GRID, 256>>>(emb);
    triplet_kernel<<<NB * 32 / 256, 256>>>(emb);
    finalize_kernel<<<1, 1>>>(out);
}